// round 1
// baseline (speedup 1.0000x reference)
#include <cuda_runtime.h>

#define CHN 128
#define TT  300
#define KK  30
#define NST 16
#define DTR 8

struct Params {
    const float* x;
    const float* ln_g;
    const float* ln_b;
    const float* fp[11];   // Win, bin, convw, convb, Wx, Wdt, bdt, Alog, D, Wout, bout
    const float* bp[11];
    const float* comb_W;
    const float* comb_b;
    float* out;
};

// Shared layout (floats)
#define OFF_XN    0                   // 30*128
#define OFF_XP    3840                // 30*128
#define OFF_YS    7680                // 30*128 (z stash, then gated y)
#define OFF_OF    11520               // 30*128
#define OFF_OB    15360               // 30*128
#define OFF_DTBC  19200               // 30*40
#define OFF_WXS   20400               // 128*40
#define OFF_WDTS  25520               // 8*128
#define OFF_MU    26544               // 30
#define OFF_RS    26574               // 30
#define SMEM_FLOATS 26604

__global__ __launch_bounds__(128, 2)
void bimamba_kernel(Params P) {
    extern __shared__ float sm[];
    float* XN   = sm + OFF_XN;
    float* XP   = sm + OFF_XP;
    float* YS   = sm + OFF_YS;
    float* OF   = sm + OFF_OF;
    float* OB   = sm + OFF_OB;
    float* DTBC = sm + OFF_DTBC;
    float* WXS  = sm + OFF_WXS;
    float* WDTS = sm + OFF_WDTS;
    float* MU   = sm + OFF_MU;
    float* RS   = sm + OFF_RS;

    const int tid = threadIdx.x;
    const int d   = tid;
    const int bt  = blockIdx.x;
    const int b   = bt / TT;
    const int t   = bt - b * TT;

    // ---- load raw x row: xr[k] = x[b, d, t, k] ----
    const float* xbase = P.x + ((size_t)(b * CHN + d) * TT + t) * KK;
    float xr_[KK];
#pragma unroll
    for (int k = 0; k < KK; k++) {
        xr_[k] = xbase[k];
        XN[k * CHN + d] = xr_[k];
    }
    __syncthreads();

    // ---- LayerNorm stats over channels, per k ----
    {
        const int w = tid >> 5, lane = tid & 31;
        for (int k = w; k < KK; k += 4) {
            float s = 0.f, q = 0.f;
#pragma unroll
            for (int i = 0; i < 4; i++) {
                float v = XN[k * CHN + lane + i * 32];
                s += v; q += v * v;
            }
#pragma unroll
            for (int o = 16; o; o >>= 1) {
                s += __shfl_xor_sync(0xffffffffu, s, o);
                q += __shfl_xor_sync(0xffffffffu, q, o);
            }
            if (lane == 0) {
                float mu  = s * (1.0f / 128.0f);
                float var = q * (1.0f / 128.0f) - mu * mu;
                MU[k] = mu;
                RS[k] = rsqrtf(var + 1e-5f);
            }
        }
    }
    __syncthreads();
    {
        const float g = P.ln_g[d], be = P.ln_b[d];
#pragma unroll
        for (int k = 0; k < KK; k++)
            XN[k * CHN + d] = (xr_[k] - MU[k]) * RS[k] * g + be;
    }
    __syncthreads();

    float axp[KK], az[KK];

    for (int dir = 0; dir < 2; dir++) {
        const float* const* PP = dir ? P.bp : P.fp;
        const float* Win  = PP[0];
        const float* bin_ = PP[1];
        const float* convw = PP[2];
        const float* convb = PP[3];
        const float* Wx   = PP[4];
        const float* Wdt  = PP[5];
        const float* bdt_ = PP[6];
        const float* Alog = PP[7];
        const float* Dp_  = PP[8];
        const float* Wout = PP[9];
        const float* bout = PP[10];
        const int k0 = dir ? (KK - 1) : 0;
        const int ks = dir ? -1 : 1;

        // stage Wx, Wdt into shared (safe: all prior readers synced)
        for (int i = tid; i < CHN * 40; i += CHN) WXS[i] = Wx[i];
        for (int i = tid; i < DTR * CHN; i += CHN) WDTS[i] = Wdt[i];

        // ---- xz = xn @ Win + bin  (thread d owns output cols d and d+128) ----
        {
            const float b1 = bin_[d], b2 = bin_[CHN + d];
#pragma unroll
            for (int j = 0; j < KK; j++) { axp[j] = b1; az[j] = b2; }
#pragma unroll 1
            for (int n0 = 0; n0 < CHN; n0 += 4) {
                float w10 = Win[(n0 + 0) * 256 + d];
                float w11 = Win[(n0 + 1) * 256 + d];
                float w12 = Win[(n0 + 2) * 256 + d];
                float w13 = Win[(n0 + 3) * 256 + d];
                float w20 = Win[(n0 + 0) * 256 + CHN + d];
                float w21 = Win[(n0 + 1) * 256 + CHN + d];
                float w22 = Win[(n0 + 2) * 256 + CHN + d];
                float w23 = Win[(n0 + 3) * 256 + CHN + d];
                const float* rp = XN + k0 * CHN + n0;
                const int rstep = ks * CHN;
#pragma unroll
                for (int j = 0; j < KK; j++) {
                    const float4 v = *(const float4*)rp;
                    rp += rstep;
                    axp[j] = fmaf(v.x, w10, fmaf(v.y, w11, fmaf(v.z, w12, fmaf(v.w, w13, axp[j]))));
                    az[j]  = fmaf(v.x, w20, fmaf(v.y, w21, fmaf(v.z, w22, fmaf(v.w, w23, az[j]))));
                }
            }
        }

        // ---- causal depthwise conv (width 4) + SiLU; stash z ----
        {
            const float cw0 = convw[d * 4 + 0], cw1 = convw[d * 4 + 1];
            const float cw2 = convw[d * 4 + 2], cw3 = convw[d * 4 + 3];
            const float cb = convb[d];
            float p1 = 0.f, p2 = 0.f, p3 = 0.f;
#pragma unroll
            for (int j = 0; j < KK; j++) {
                YS[j * CHN + d] = az[j];
                const float raw = axp[j];
                float s = cb + cw0 * p3 + cw1 * p2 + cw2 * p1 + cw3 * raw;
                p3 = p2; p2 = p1; p1 = raw;
                XP[j * CHN + d] = __fdividef(s, 1.f + __expf(-s));   // silu
            }
        }
        __syncthreads();

        // ---- xdbl = xp @ Wx  (cooperative: 30*40 outputs) ----
        for (int idx = tid; idx < KK * 40; idx += CHN) {
            const int j = idx / 40;
            const int c = idx - j * 40;
            const float* xrow = XP + j * CHN;
            float a = 0.f;
#pragma unroll 1
            for (int n0 = 0; n0 < CHN; n0 += 4) {
                const float4 v = *(const float4*)(xrow + n0);
                a = fmaf(v.x, WXS[(n0 + 0) * 40 + c], a);
                a = fmaf(v.y, WXS[(n0 + 1) * 40 + c], a);
                a = fmaf(v.z, WXS[(n0 + 2) * 40 + c], a);
                a = fmaf(v.w, WXS[(n0 + 3) * 40 + c], a);
            }
            DTBC[idx] = a;
        }
        __syncthreads();

        // ---- selective scan (thread d owns channel d; h[16] in registers) ----
        {
            float A_[NST];
#pragma unroll
            for (int s = 0; s < NST; s++) A_[s] = -__expf(Alog[d * NST + s]);
            const float Dp = Dp_[d];
            const float bdt = bdt_[d];
            float h[NST];
#pragma unroll
            for (int s = 0; s < NST; s++) h[s] = 0.f;
#pragma unroll 1
            for (int j = 0; j < KK; j++) {
                const float* row = DTBC + j * 40;
                float acc = bdt;
#pragma unroll
                for (int r = 0; r < DTR; r++) acc = fmaf(row[r], WDTS[r * CHN + d], acc);
                const float dt = (acc > 20.f) ? acc : log1pf(__expf(acc));
                const float xv = XP[j * CHN + d];
                const float dtx = dt * xv;
                float y = 0.f;
#pragma unroll
                for (int s = 0; s < NST; s++) {
                    const float dA = __expf(dt * A_[s]);
                    h[s] = fmaf(dA, h[s], dtx * row[8 + s]);
                    y = fmaf(h[s], row[24 + s], y);
                }
                y = fmaf(xv, Dp, y);
                const float z = YS[j * CHN + d];
                const float g = __fdividef(z, 1.f + __expf(-z));
                YS[j * CHN + d] = y * g;
            }
        }
        __syncthreads();

        // ---- out = y @ Wout + bout ----
        {
            const float bo = bout[d];
#pragma unroll
            for (int j = 0; j < KK; j++) axp[j] = bo;
#pragma unroll 1
            for (int n0 = 0; n0 < CHN; n0 += 4) {
                float w0 = Wout[(n0 + 0) * CHN + d];
                float w1 = Wout[(n0 + 1) * CHN + d];
                float w2 = Wout[(n0 + 2) * CHN + d];
                float w3 = Wout[(n0 + 3) * CHN + d];
                const float* yp = YS + n0;
#pragma unroll
                for (int j = 0; j < KK; j++) {
                    const float4 v = *(const float4*)(yp + j * CHN);
                    axp[j] = fmaf(v.x, w0, fmaf(v.y, w1, fmaf(v.z, w2, fmaf(v.w, w3, axp[j]))));
                }
            }
            float* OUT = dir ? OB : OF;
#pragma unroll
            for (int j = 0; j < KK; j++) OUT[(k0 + ks * j) * CHN + d] = axp[j];
        }
        __syncthreads();
    }

    // ---- comb: out = [of, ob] @ comb_W + comb_b + xr ----
    {
        float acc[KK];
        const float cb = P.comb_b[d];
#pragma unroll
        for (int k = 0; k < KK; k++) acc[k] = cb + xr_[k];
#pragma unroll 1
        for (int n0 = 0; n0 < CHN; n0 += 4) {
            float f0 = P.comb_W[(n0 + 0) * CHN + d];
            float f1 = P.comb_W[(n0 + 1) * CHN + d];
            float f2 = P.comb_W[(n0 + 2) * CHN + d];
            float f3 = P.comb_W[(n0 + 3) * CHN + d];
            float g0 = P.comb_W[(CHN + n0 + 0) * CHN + d];
            float g1 = P.comb_W[(CHN + n0 + 1) * CHN + d];
            float g2 = P.comb_W[(CHN + n0 + 2) * CHN + d];
            float g3 = P.comb_W[(CHN + n0 + 3) * CHN + d];
#pragma unroll
            for (int k = 0; k < KK; k++) {
                const float4 u = *(const float4*)(OF + k * CHN + n0);
                const float4 v = *(const float4*)(OB + k * CHN + n0);
                acc[k] = fmaf(u.x, f0, fmaf(u.y, f1, fmaf(u.z, f2, fmaf(u.w, f3, acc[k]))));
                acc[k] = fmaf(v.x, g0, fmaf(v.y, g1, fmaf(v.z, g2, fmaf(v.w, g3, acc[k]))));
            }
        }
        float* obase = P.out + ((size_t)(b * CHN + d) * TT + t) * KK;
#pragma unroll
        for (int k = 0; k < KK; k++) obase[k] = acc[k];
    }
}

extern "C" void kernel_launch(void* const* d_in, const int* in_sizes, int n_in,
                              void* d_out, int out_size) {
    Params P;
    P.x    = (const float*)d_in[0];
    P.ln_g = (const float*)d_in[1];
    P.ln_b = (const float*)d_in[2];
    for (int i = 0; i < 11; i++) {
        P.fp[i] = (const float*)d_in[3 + i];
        P.bp[i] = (const float*)d_in[14 + i];
    }
    P.comb_W = (const float*)d_in[25];
    P.comb_b = (const float*)d_in[26];
    P.out = (float*)d_out;

    const int smem_bytes = SMEM_FLOATS * (int)sizeof(float);
    cudaFuncSetAttribute(bimamba_kernel, cudaFuncAttributeMaxDynamicSharedMemorySize, smem_bytes);
    bimamba_kernel<<<8 * TT, CHN, smem_bytes>>>(P);
}